// round 4
// baseline (speedup 1.0000x reference)
#include <cuda_runtime.h>
#include <cstdint>

#define BB 4
#define NNN 2048
#define KK 30
#define NNODE (BB*NNN)        // 8192
#define NEDGE (NNODE*KK)      // 245760
#define FSTR 417              // 416 features + 1 pad
#define EPB 32                // edges per GEMM block

typedef unsigned long long ull;

// scratch: __device__ globals (allocation-free rule)
__device__ float g_coords5[NNODE*15];   // N,Ca,C,O,Cb xyz per node
__device__ float g_ca[NNODE*3];
__device__ int   g_eidx[NEDGE];

// pair table: atom of node i, atom of neighbor j; N=0,Ca=1,C=2,O=3,Cb=4
// p0 = (Ca,Ca) = D_neighbors, then the 24 reference pairs in order
__constant__ int c_pa[25] = {1, 0,2,3,4, 1,1,1,1, 0,0,0, 4,4, 3, 0,2,3,4, 2,3,4, 2,3, 2};
__constant__ int c_pb[25] = {1, 0,2,3,4, 0,2,3,4, 2,3,4, 2,3, 2, 1,1,1,1, 0,0,0, 4,4, 3};

// RBF: mu_k = 2 + k*DEL, DEL=4/3, sigma=1.25
#define RBF_DEL 1.33333333333f
#define RBF_A   1.70666666667f   // 2*DEL/sigma^2
#define RBF_B   1.13777777778f   // DEL^2/sigma^2
#define RBF_Q   0.10273983f      // exp(-2*RBF_B)

// ---------------------------------------------------------------- k_prep
__global__ void k_prep(const float* __restrict__ X)
{
    int gid = blockIdx.x * blockDim.x + threadIdx.x;
    if (gid >= NNODE) return;
    const float* x = X + gid*12;
    float Nx=x[0],  Ny=x[1],  Nz=x[2];
    float Cax=x[3], Cay=x[4], Caz=x[5];
    float Cx=x[6],  Cy=x[7],  Cz=x[8];
    float Ox=x[9],  Oy=x[10], Oz=x[11];
    float bx=Cax-Nx, by=Cay-Ny, bz=Caz-Nz;
    float cx=Cx-Cax, cy=Cy-Cay, cz=Cz-Caz;
    float ax = by*cz - bz*cy;
    float ay = bz*cx - bx*cz;
    float az = bx*cy - by*cx;
    float Cbx = -0.58273431f*ax + 0.56802827f*bx - 0.54067466f*cx + Cax;
    float Cby = -0.58273431f*ay + 0.56802827f*by - 0.54067466f*cy + Cay;
    float Cbz = -0.58273431f*az + 0.56802827f*bz - 0.54067466f*cz + Caz;
    float* o = g_coords5 + gid*15;
    o[0]=Nx;   o[1]=Ny;   o[2]=Nz;
    o[3]=Cax;  o[4]=Cay;  o[5]=Caz;
    o[6]=Cx;   o[7]=Cy;   o[8]=Cz;
    o[9]=Ox;   o[10]=Oy;  o[11]=Oz;
    o[12]=Cbx; o[13]=Cby; o[14]=Cbz;
    g_ca[gid*3+0]=Cax; g_ca[gid*3+1]=Cay; g_ca[gid*3+2]=Caz;
}

// ---------------------------------------------------------------- k_topk
// exact ascending top-30 per node; packed key = (D_bits<<32)|j gives
// lower-index tie-break and monotonic unsigned order for D >= 0.
__global__ void __launch_bounds__(256) k_topk(
    const float* __restrict__ mask,
    float* __restrict__ out_tail,
    int write_tail)
{
    __shared__ ull   keys[NNN];
    __shared__ ull   wred[8];
    __shared__ float fred[8];

    int gid = blockIdx.x;
    int b   = gid >> 11;
    int tid = threadIdx.x;
    int lid = tid & 31, wid = tid >> 5;

    float cix = g_ca[gid*3+0], ciy = g_ca[gid*3+1], ciz = g_ca[gid*3+2];
    float mi  = mask[gid];
    const float* cab = g_ca + (size_t)(b << 11) * 3;
    const float* mb  = mask + (b << 11);

    // pass 1: distances, packed keys, row max
    float lmax = 0.f;
    for (int j = tid; j < NNN; j += 256) {
        float dx = cab[j*3+0]-cix, dy = cab[j*3+1]-ciy, dz = cab[j*3+2]-ciz;
        float D  = mi * mb[j] * __fsqrt_rn(dx*dx + dy*dy + dz*dz + 1e-6f);
        keys[j]  = ((ull)__float_as_uint(D) << 32) | (unsigned)j;
        lmax = fmaxf(lmax, D);
    }
    #pragma unroll
    for (int m = 16; m > 0; m >>= 1)
        lmax = fmaxf(lmax, __shfl_xor_sync(0xFFFFFFFFu, lmax, m));
    if (lid == 0) fred[wid] = lmax;
    __syncthreads();
    float Dmax = fred[0];
    #pragma unroll
    for (int w = 1; w < 8; w++) Dmax = fmaxf(Dmax, fred[w]);

    // pass 2: D_adjust = D + (1-m2)*Dmax (no-op when mask==1)
    for (int j = tid; j < NNN; j += 256) {
        float m2 = mi * mb[j];
        if (m2 != 1.0f) {
            float D = __uint_as_float((unsigned)(keys[j] >> 32));
            float Da = D + (1.0f - m2) * Dmax;
            keys[j] = ((ull)__float_as_uint(Da) << 32) | (unsigned)j;
        }
    }
    __syncthreads();

    // 30 argmin extractions, shuffle-based reduction (2 barriers each)
    for (int k = 0; k < KK; k++) {
        ull lm = 0xFFFFFFFFFFFFFFFFull;
        #pragma unroll
        for (int r = 0; r < 8; r++) {
            ull v = keys[tid + r*256];
            lm = (v < lm) ? v : lm;
        }
        #pragma unroll
        for (int m = 16; m > 0; m >>= 1) {
            ull o = __shfl_xor_sync(0xFFFFFFFFu, lm, m);
            lm = (o < lm) ? o : lm;
        }
        if (lid == 0) wred[wid] = lm;
        __syncthreads();
        if (tid == 0) {
            ull best = wred[0];
            #pragma unroll
            for (int w = 1; w < 8; w++) { ull v = wred[w]; best = (v < best) ? v : best; }
            int bj = (int)(best & 0xFFFFFFFFull);
            g_eidx[gid*KK + k] = bj;
            if (write_tail) out_tail[gid*KK + k] = (float)bj;
            keys[bj] = 0xFFFFFFFFFFFFFFFFull;
        }
        __syncthreads();
    }
}

// ---------------------------------------------------------------- k_edge
// features (3-MUFU RBF recurrence) + f32x2 GEMM + fused LayerNorm.
// 32 edges/block, 128 threads, thread tile 4 edges x 4 channel-pairs.
extern __shared__ float smem_dyn[];

__global__ void __launch_bounds__(128) k_edge(
    const int*   __restrict__ ridx,
    const int*   __restrict__ chain,
    const float* __restrict__ W_pos,
    const float* __restrict__ b_pos,
    const float* __restrict__ W_edge,
    const float* __restrict__ ln_s,
    const float* __restrict__ ln_o,
    float*       __restrict__ out)
{
    float* feat = smem_dyn;               // EPB*FSTR
    float* Wsh  = smem_dyn + EPB*FSTR;    // 32*128
    __shared__ int sm_gi[EPB], sm_gj[EPB], sm_dp[EPB];

    int tid = threadIdx.x;
    int e0  = blockIdx.x * EPB;

    if (tid < EPB) {
        int edge = e0 + tid;
        int node = edge / KK;
        int b    = node >> 11;
        int gj   = (b << 11) + g_eidx[edge];
        sm_gi[tid] = node; sm_gj[tid] = gj;
        int off = ridx[node] - ridx[gj];
        sm_dp[tid] = (chain[node] == chain[gj]) ? min(max(off + 32, 0), 64) : 65;
    }
    __syncthreads();

    // positional features
    for (int t = tid; t < EPB*16; t += 128) {
        int e = t >> 4, k = t & 15;
        feat[e*FSTR + k] = W_pos[sm_dp[e]*16 + k] + b_pos[k];
    }

    // 25 distance->16-RBF blocks per edge (800 tasks / 128 threads)
    for (int t = tid; t < EPB*25; t += 128) {
        int e = t / 25;
        int p = t - e*25;
        const float* pa = g_coords5 + sm_gi[e]*15 + c_pa[p]*3;
        const float* pb = g_coords5 + sm_gj[e]*15 + c_pb[p]*3;
        float dx = pa[0]-pb[0], dy = pa[1]-pb[1], dz = pa[2]-pb[2];
        float d  = __fsqrt_rn(dx*dx + dy*dy + dz*dz + 1e-6f);

        float* dst = feat + e*FSTR + 16 + p*16;
        int ka = __float2int_rn((d - 2.0f) * 0.75f);
        ka = max(0, min(15, ka));
        float u  = d - (2.0f + RBF_DEL * (float)ka);
        float tt = u * 0.8f;                    // u/sigma
        float fa = __expf(-tt*tt);
        float ru = __expf(RBF_A*u - RBF_B);     // ratio k->k+1 at anchor
        float rd = __fdividef(RBF_Q, ru);       // ratio k->k-1 at anchor
        dst[ka] = fa;
        float f = fa, r = ru;
        for (int k2 = ka+1; k2 < 16; k2++) { f *= r; dst[k2] = f; r *= RBF_Q; }
        f = fa; r = rd;
        for (int k2 = ka-1; k2 >= 0; k2--) { f *= r; dst[k2] = f; r *= RBF_Q; }
    }
    __syncthreads();

    // GEMM: acc[edge 0..3][pair m], pair m -> channels (2*(cg+16m), +1)
    int eg = tid >> 4;   // 0..7
    int cg = tid & 15;   // 0..15
    ull acc[4][4];
    #pragma unroll
    for (int e = 0; e < 4; e++)
        #pragma unroll
        for (int m = 0; m < 4; m++) acc[e][m] = 0ull;

    for (int ch = 0; ch < 13; ++ch) {
        const float4* src  = (const float4*)(W_edge + ch*4096);
        float4*       dst4 = (float4*)Wsh;
        #pragma unroll
        for (int v = 0; v < 8; ++v) dst4[tid + v*128] = src[tid + v*128];
        __syncthreads();

        int base = ch*32;
        #pragma unroll 4
        for (int t = 0; t < 32; ++t) {
            const float* wrow = Wsh + t*128 + 2*cg;
            ull w0 = *(const ull*)(wrow);
            ull w1 = *(const ull*)(wrow + 32);
            ull w2 = *(const ull*)(wrow + 64);
            ull w3 = *(const ull*)(wrow + 96);
            #pragma unroll
            for (int e = 0; e < 4; e++) {
                float fv = feat[(eg*4 + e)*FSTR + base + t];
                ull fp;
                asm("mov.b64 %0, {%1, %1};" : "=l"(fp) : "r"(__float_as_uint(fv)));
                asm("fma.rn.f32x2 %0, %1, %2, %0;" : "+l"(acc[e][0]) : "l"(fp), "l"(w0));
                asm("fma.rn.f32x2 %0, %1, %2, %0;" : "+l"(acc[e][1]) : "l"(fp), "l"(w1));
                asm("fma.rn.f32x2 %0, %1, %2, %0;" : "+l"(acc[e][2]) : "l"(fp), "l"(w2));
                asm("fma.rn.f32x2 %0, %1, %2, %0;" : "+l"(acc[e][3]) : "l"(fp), "l"(w3));
            }
        }
        __syncthreads();
    }

    // fused LayerNorm: one edge's 128 channels live in 16 lanes
    float ls[8], lo_[8];
    #pragma unroll
    for (int m = 0; m < 4; m++) {
        int c = 2*(cg + 16*m);
        ls[2*m]   = ln_s[c];   ls[2*m+1]  = ln_s[c+1];
        lo_[2*m]  = ln_o[c];   lo_[2*m+1] = ln_o[c+1];
    }
    #pragma unroll
    for (int e = 0; e < 4; e++) {
        float v[8];
        #pragma unroll
        for (int m = 0; m < 4; m++) {
            v[2*m]   = __uint_as_float((unsigned)(acc[e][m] & 0xFFFFFFFFull));
            v[2*m+1] = __uint_as_float((unsigned)(acc[e][m] >> 32));
        }
        float s = 0.f, s2 = 0.f;
        #pragma unroll
        for (int q = 0; q < 8; q++) { s += v[q]; s2 += v[q]*v[q]; }
        #pragma unroll
        for (int msk = 1; msk < 16; msk <<= 1) {
            s  += __shfl_xor_sync(0xFFFFFFFFu, s,  msk);
            s2 += __shfl_xor_sync(0xFFFFFFFFu, s2, msk);
        }
        float mean = s  * (1.0f/128.0f);
        float var  = s2 * (1.0f/128.0f) - mean*mean;
        float rstd = rsqrtf(var + 1e-5f);
        size_t ob = (size_t)(e0 + eg*4 + e) * 128;
        #pragma unroll
        for (int m = 0; m < 4; m++) {
            float2 o;
            o.x = (v[2*m]   - mean)*rstd*ls[2*m]   + lo_[2*m];
            o.y = (v[2*m+1] - mean)*rstd*ls[2*m+1] + lo_[2*m+1];
            *(float2*)(out + ob + 2*(cg + 16*m)) = o;
        }
    }
}

// ----------------------------------------------------------------
extern "C" void kernel_launch(void* const* d_in, const int* in_sizes, int n_in,
                              void* d_out, int out_size)
{
    const float* X      = (const float*)d_in[0];
    const float* mask   = (const float*)d_in[1];
    const int*   ridx   = (const int*)  d_in[2];
    const int*   chain  = (const int*)  d_in[3];
    const float* W_pos  = (const float*)d_in[4];
    const float* b_pos  = (const float*)d_in[5];
    const float* W_edge = (const float*)d_in[6];
    const float* ln_s   = (const float*)d_in[7];
    const float* ln_o   = (const float*)d_in[8];
    float* out = (float*)d_out;

    int write_tail = (out_size > NEDGE*128) ? 1 : 0;
    float* tail = out + (size_t)NEDGE*128;

    static int smem_set = 0;
    int smem_bytes = (EPB*FSTR + 32*128) * (int)sizeof(float);  // 69760
    if (!smem_set) {
        cudaFuncSetAttribute(k_edge, cudaFuncAttributeMaxDynamicSharedMemorySize,
                             smem_bytes);
        smem_set = 1;
    }

    k_prep<<<(NNODE + 255)/256, 256>>>(X);
    k_topk<<<NNODE, 256>>>(mask, tail, write_tail);
    k_edge<<<NEDGE/EPB, 128, smem_bytes>>>(ridx, chain, W_pos, b_pos, W_edge,
                                           ln_s, ln_o, out);
}

// round 6
// speedup vs baseline: 2.6632x; 2.6632x over previous
#include <cuda_runtime.h>
#include <cstdint>

#define BB 4
#define NNN 2048
#define KK 30
#define NNODE (BB*NNN)        // 8192
#define NEDGE (NNODE*KK)      // 245760
#define EPB 128               // edges (M) per k_edge block
#define NCH 13                // K chunks of 32 (K = 416)
#define ASTR 36               // padded row stride (words) -> conflict-free frags

typedef unsigned long long ull;
typedef unsigned int uint;

// scratch: __device__ globals (allocation-free rule)
__device__ float g_coords5[NNODE*15];   // N,Ca,C,O,Cb xyz per node
__device__ float g_ca[NNODE*3];
__device__ int   g_eidx[NEDGE];

// pair table: atom of node i, atom of neighbor j; N=0,Ca=1,C=2,O=3,Cb=4
__constant__ int c_pa[25] = {1, 0,2,3,4, 1,1,1,1, 0,0,0, 4,4, 3, 0,2,3,4, 2,3,4, 2,3, 2};
__constant__ int c_pb[25] = {1, 0,2,3,4, 0,2,3,4, 2,3,4, 2,3, 2, 1,1,1,1, 0,0,0, 4,4, 3};

#define RBF_DEL 1.33333333333f   // (22-2)/15
#define RBF_INVS 0.8f            // 1/sigma, sigma = 1.25

// ---------------------------------------------------------------- helpers
__device__ __forceinline__ uint f2tf32(float v){
    uint r; asm("cvt.rna.tf32.f32 %0, %1;" : "=r"(r) : "f"(v)); return r;
}
__device__ __forceinline__ void mma8(float* d, const uint* a, const uint* b){
    asm volatile("mma.sync.aligned.m16n8k8.row.col.f32.tf32.tf32.f32 "
        "{%0,%1,%2,%3}, {%4,%5,%6,%7}, {%8,%9}, {%0,%1,%2,%3};"
        : "+f"(d[0]), "+f"(d[1]), "+f"(d[2]), "+f"(d[3])
        : "r"(a[0]), "r"(a[1]), "r"(a[2]), "r"(a[3]), "r"(b[0]), "r"(b[1]));
}

// ---------------------------------------------------------------- k_prep
__global__ void k_prep(const float* __restrict__ X)
{
    int gid = blockIdx.x * blockDim.x + threadIdx.x;
    if (gid >= NNODE) return;
    const float* x = X + gid*12;
    float Nx=x[0],  Ny=x[1],  Nz=x[2];
    float Cax=x[3], Cay=x[4], Caz=x[5];
    float Cx=x[6],  Cy=x[7],  Cz=x[8];
    float Ox=x[9],  Oy=x[10], Oz=x[11];
    float bx=Cax-Nx, by=Cay-Ny, bz=Caz-Nz;
    float cx=Cx-Cax, cy=Cy-Cay, cz=Cz-Caz;
    float ax = by*cz - bz*cy;
    float ay = bz*cx - bx*cz;
    float az = bx*cy - by*cx;
    float Cbx = -0.58273431f*ax + 0.56802827f*bx - 0.54067466f*cx + Cax;
    float Cby = -0.58273431f*ay + 0.56802827f*by - 0.54067466f*cy + Cay;
    float Cbz = -0.58273431f*az + 0.56802827f*bz - 0.54067466f*cz + Caz;
    float* o = g_coords5 + gid*15;
    o[0]=Nx;   o[1]=Ny;   o[2]=Nz;
    o[3]=Cax;  o[4]=Cay;  o[5]=Caz;
    o[6]=Cx;   o[7]=Cy;   o[8]=Cz;
    o[9]=Ox;   o[10]=Oy;  o[11]=Oz;
    o[12]=Cbx; o[13]=Cby; o[14]=Cbz;
    g_ca[gid*3+0]=Cax; g_ca[gid*3+1]=Cay; g_ca[gid*3+2]=Caz;
}

// ---------------------------------------------------------------- k_topk
// exact ascending top-30; hierarchical: 8 warps own 256-key segments,
// only the segment that lost its min rescans each round.
__global__ void __launch_bounds__(256) k_topk(
    const float* __restrict__ mask,
    float* __restrict__ out_tail,
    int write_tail)
{
    __shared__ ull   keys[NNN];
    __shared__ ull   wmin[8];
    __shared__ float fred[8];
    __shared__ int   s_owner;

    int gid = blockIdx.x;
    int b   = gid >> 11;
    int tid = threadIdx.x;
    int lid = tid & 31, wid = tid >> 5;

    float cix = g_ca[gid*3+0], ciy = g_ca[gid*3+1], ciz = g_ca[gid*3+2];
    float mi  = mask[gid];
    const float* cab = g_ca + (size_t)(b << 11) * 3;
    const float* mb  = mask + (b << 11);

    // pass 1: distances, packed keys, row max
    float lmax = 0.f;
    for (int j = tid; j < NNN; j += 256) {
        float dx = cab[j*3+0]-cix, dy = cab[j*3+1]-ciy, dz = cab[j*3+2]-ciz;
        float D  = mi * mb[j] * __fsqrt_rn(dx*dx + dy*dy + dz*dz + 1e-6f);
        keys[j]  = ((ull)__float_as_uint(D) << 32) | (unsigned)j;
        lmax = fmaxf(lmax, D);
    }
    #pragma unroll
    for (int m = 16; m > 0; m >>= 1)
        lmax = fmaxf(lmax, __shfl_xor_sync(0xFFFFFFFFu, lmax, m));
    if (lid == 0) fred[wid] = lmax;
    __syncthreads();
    float Dmax = fred[0];
    #pragma unroll
    for (int w = 1; w < 8; w++) Dmax = fmaxf(Dmax, fred[w]);

    // pass 2: D_adjust (no-op when mask==1)
    for (int j = tid; j < NNN; j += 256) {
        float m2 = mi * mb[j];
        if (m2 != 1.0f) {
            float D = __uint_as_float((unsigned)(keys[j] >> 32));
            float Da = D + (1.0f - m2) * Dmax;
            keys[j] = ((ull)__float_as_uint(Da) << 32) | (unsigned)j;
        }
    }
    __syncthreads();

    // per-warp segment min cache
    {
        ull lm = 0xFFFFFFFFFFFFFFFFull;
        int base = wid << 8;
        #pragma unroll
        for (int r = 0; r < 8; r++) {
            ull v = keys[base + lid + (r<<5)];
            lm = (v < lm) ? v : lm;
        }
        #pragma unroll
        for (int m = 16; m > 0; m >>= 1) {
            ull o = __shfl_xor_sync(0xFFFFFFFFu, lm, m);
            lm = (o < lm) ? o : lm;
        }
        if (lid == 0) wmin[wid] = lm;
    }
    __syncthreads();

    for (int k = 0; k < KK; k++) {
        if (tid == 0) {
            ull best = wmin[0]; int ow = 0;
            #pragma unroll
            for (int w = 1; w < 8; w++) {
                ull v = wmin[w];
                if (v < best) { best = v; ow = w; }
            }
            int bj = (int)(best & 0xFFFFFFFFull);
            g_eidx[gid*KK + k] = bj;
            if (write_tail) out_tail[gid*KK + k] = (float)bj;
            keys[bj] = 0xFFFFFFFFFFFFFFFFull;
            s_owner = ow;
        }
        __syncthreads();
        if (wid == s_owner) {
            ull lm = 0xFFFFFFFFFFFFFFFFull;
            int base = wid << 8;
            #pragma unroll
            for (int r = 0; r < 8; r++) {
                ull v = keys[base + lid + (r<<5)];
                lm = (v < lm) ? v : lm;
            }
            #pragma unroll
            for (int m = 16; m > 0; m >>= 1) {
                ull o = __shfl_xor_sync(0xFFFFFFFFu, lm, m);
                lm = (o < lm) ? o : lm;
            }
            if (lid == 0) wmin[wid] = lm;
        }
        __syncthreads();
    }
}

// ---------------------------------------------------------------- k_edge
// D[128 edges, 128 ch] = A[128, 416] * W^T[128, 416] via mma.sync tf32,
// features generated per 32-wide K chunk into SMEM (tf32 bits), fused LN.
extern __shared__ uint sm_u[];

__global__ void __launch_bounds__(256, 2) k_edge(
    const int*   __restrict__ ridx,
    const int*   __restrict__ chain,
    const float* __restrict__ Wp,
    const float* __restrict__ bp,
    const float* __restrict__ We,
    const float* __restrict__ lns,
    const float* __restrict__ lno,
    float*       __restrict__ out)
{
    uint* As = sm_u;               // [128][ASTR]
    uint* Bs = sm_u + 128*ASTR;    // [128][ASTR]
    __shared__ int   s_gi[EPB], s_gj[EPB], s_dp[EPB];
    __shared__ float s_lns[128], s_lno[128];

    int tid = threadIdx.x, wid = tid >> 5, lid = tid & 31;
    int e0  = blockIdx.x * EPB;

    if (tid < EPB) {
        int edge = e0 + tid;
        int node = edge / KK;
        int bb   = node >> 11;
        int gj   = (bb << 11) + g_eidx[edge];
        s_gi[tid] = node; s_gj[tid] = gj;
        int off = ridx[node] - ridx[gj];
        s_dp[tid] = (chain[node] == chain[gj]) ? min(max(off + 32, 0), 64) : 65;
        s_lns[tid] = lns[tid]; s_lno[tid] = lno[tid];
    }
    __syncthreads();

    int mw = wid >> 1, nw = wid & 1;
    int m0 = mw << 5, n0 = nw << 6;
    int lg = lid >> 2, lt = lid & 3;

    int fe  = tid >> 1;        // row (m for A, n for B)
    int fbl = tid & 1;         // 16-wide k half within chunk

    float acc[2][8][4];
    #pragma unroll
    for (int mt = 0; mt < 2; mt++)
        #pragma unroll
        for (int nt = 0; nt < 8; nt++)
            #pragma unroll
            for (int q = 0; q < 4; q++) acc[mt][nt][q] = 0.f;

    for (int c = 0; c < NCH; ++c) {
        // ---- stage B: Bs[n][kk] = tf32(We[(32c+kk)*128 + n])
        {
            const float* col = We + (size_t)(c*32 + fbl*16)*128 + fe;
            uint* bd = Bs + fe*ASTR + fbl*16;
            #pragma unroll
            for (int j = 0; j < 16; j++)
                bd[j] = f2tf32(col[(size_t)j*128]);
        }
        // ---- generate A: feature block fb = 2c + fbl for edge fe
        {
            uint* ad = As + fe*ASTR + fbl*16;
            int fb = 2*c + fbl;
            if (fb == 0) {
                const float* wrow = Wp + s_dp[fe]*16;
                #pragma unroll
                for (int j = 0; j < 16; j++)
                    ad[j] = f2tf32(wrow[j] + bp[j]);
            } else {
                int p = fb - 1;
                const float* pa = g_coords5 + s_gi[fe]*15 + c_pa[p]*3;
                const float* pq = g_coords5 + s_gj[fe]*15 + c_pb[p]*3;
                float dx = pa[0]-pq[0], dy = pa[1]-pq[1], dz = pa[2]-pq[2];
                float d  = __fsqrt_rn(dx*dx + dy*dy + dz*dz + 1e-6f);
                #pragma unroll
                for (int j = 0; j < 16; j++) {
                    float u = (d - (2.0f + RBF_DEL*(float)j)) * RBF_INVS;
                    ad[j] = f2tf32(__expf(-u*u));
                }
            }
        }
        __syncthreads();

        // ---- 4 k-steps of m16n8k8
        #pragma unroll
        for (int ks = 0; ks < 4; ks++) {
            int kb = ks << 3;
            uint a[2][4], bfr[8][2];
            #pragma unroll
            for (int mt = 0; mt < 2; mt++) {
                const uint* ap = As + (m0 + 16*mt + lg)*ASTR + kb + lt;
                a[mt][0] = ap[0];
                a[mt][1] = ap[8*ASTR];
                a[mt][2] = ap[4];
                a[mt][3] = ap[8*ASTR + 4];
            }
            #pragma unroll
            for (int nt = 0; nt < 8; nt++) {
                const uint* bptr = Bs + (n0 + 8*nt + lg)*ASTR + kb + lt;
                bfr[nt][0] = bptr[0];
                bfr[nt][1] = bptr[4];
            }
            #pragma unroll
            for (int mt = 0; mt < 2; mt++)
                #pragma unroll
                for (int nt = 0; nt < 8; nt++)
                    mma8(acc[mt][nt], a[mt], bfr[nt]);
        }
        __syncthreads();
    }

    // ---- fused LayerNorm epilogue
    // row-partials over this warp's 64 cols, reduce over the 4 lanes of a group
    float2* red = (float2*)sm_u;   // [128 rows][2 col-halves]
    #pragma unroll
    for (int mt = 0; mt < 2; mt++) {
        #pragma unroll
        for (int hf = 0; hf < 2; hf++) {
            float s1 = 0.f, s2 = 0.f;
            #pragma unroll
            for (int nt = 0; nt < 8; nt++) {
                float v0 = acc[mt][nt][2*hf], v1 = acc[mt][nt][2*hf+1];
                s1 += v0 + v1; s2 += v0*v0 + v1*v1;
            }
            #pragma unroll
            for (int m = 1; m < 4; m <<= 1) {
                s1 += __shfl_xor_sync(0xFFFFFFFFu, s1, m);
                s2 += __shfl_xor_sync(0xFFFFFFFFu, s2, m);
            }
            if (lt == 0) {
                int row = m0 + 16*mt + 8*hf + lg;
                red[row*2 + nw] = make_float2(s1, s2);
            }
        }
    }
    __syncthreads();

    #pragma unroll
    for (int mt = 0; mt < 2; mt++) {
        #pragma unroll
        for (int hf = 0; hf < 2; hf++) {
            int row = m0 + 16*mt + 8*hf + lg;
            float2 r0 = red[row*2 + 0], r1 = red[row*2 + 1];
            float s1 = r0.x + r1.x, s2 = r0.y + r1.y;
            float mean = s1 * (1.0f/128.0f);
            float var  = s2 * (1.0f/128.0f) - mean*mean;
            float rstd = rsqrtf(var + 1e-5f);
            float* orow = out + (size_t)(e0 + row) * 128;
            #pragma unroll
            for (int nt = 0; nt < 8; nt++) {
                int col = n0 + nt*8 + 2*lt;
                float v0 = acc[mt][nt][2*hf], v1 = acc[mt][nt][2*hf+1];
                float2 o;
                o.x = (v0 - mean)*rstd*s_lns[col]   + s_lno[col];
                o.y = (v1 - mean)*rstd*s_lns[col+1] + s_lno[col+1];
                *(float2*)(orow + col) = o;
            }
        }
    }
}

// ----------------------------------------------------------------
extern "C" void kernel_launch(void* const* d_in, const int* in_sizes, int n_in,
                              void* d_out, int out_size)
{
    const float* X      = (const float*)d_in[0];
    const float* mask   = (const float*)d_in[1];
    const int*   ridx   = (const int*)  d_in[2];
    const int*   chain  = (const int*)  d_in[3];
    const float* W_pos  = (const float*)d_in[4];
    const float* b_pos  = (const float*)d_in[5];
    const float* W_edge = (const float*)d_in[6];
    const float* ln_s   = (const float*)d_in[7];
    const float* ln_o   = (const float*)d_in[8];
    float* out = (float*)d_out;

    int write_tail = (out_size > NEDGE*128) ? 1 : 0;
    float* tail = out + (size_t)NEDGE*128;

    int smem_bytes = 2 * 128 * ASTR * (int)sizeof(uint);   // 36864 < 48KB

    k_prep<<<(NNODE + 255)/256, 256>>>(X);
    k_topk<<<NNODE, 256>>>(mask, tail, write_tail);
    k_edge<<<NEDGE/EPB, 256, smem_bytes>>>(ridx, chain, W_pos, b_pos, W_edge,
                                           ln_s, ln_o, out);
}

// round 7
// speedup vs baseline: 3.5688x; 1.3401x over previous
#include <cuda_runtime.h>
#include <cuda_fp16.h>
#include <cstdint>

#define BB 4
#define NNN 2048
#define KK 30
#define NNODE (BB*NNN)        // 8192
#define NEDGE (NNODE*KK)      // 245760
#define EPB 128               // edges (M) per k_edge block
#define NCH 13                // K chunks of 32 (K = 416)
#define ROWB 80               // smem row stride in bytes (40 halves)

typedef unsigned long long ull;
typedef unsigned int uint;

// scratch: __device__ globals (allocation-free rule)
__device__ float g_coords5[NNODE*15];   // N,Ca,C,O,Cb xyz per node
__device__ float g_ca[NNODE*3];
__device__ int   g_eidx[NEDGE];
__device__ __align__(16) __half g_wt[128*416];   // W^T fp16: [n][k]

// pair table: atom of node i, atom of neighbor j; N=0,Ca=1,C=2,O=3,Cb=4
__constant__ int c_pa[25] = {1, 0,2,3,4, 1,1,1,1, 0,0,0, 4,4, 3, 0,2,3,4, 2,3,4, 2,3, 2};
__constant__ int c_pb[25] = {1, 0,2,3,4, 0,2,3,4, 2,3,4, 2,3, 2, 1,1,1,1, 0,0,0, 4,4, 3};

#define RBF_DEL 1.33333333333f   // (22-2)/15
#define RBF_INVS 0.8f            // 1/sigma, sigma = 1.25

// ---------------------------------------------------------------- helpers
__device__ __forceinline__ void mma16(float* d, const uint* a, const uint* b){
    asm volatile("mma.sync.aligned.m16n8k16.row.col.f32.f16.f16.f32 "
        "{%0,%1,%2,%3}, {%4,%5,%6,%7}, {%8,%9}, {%0,%1,%2,%3};"
        : "+f"(d[0]), "+f"(d[1]), "+f"(d[2]), "+f"(d[3])
        : "r"(a[0]), "r"(a[1]), "r"(a[2]), "r"(a[3]), "r"(b[0]), "r"(b[1]));
}
__device__ __forceinline__ void ldmx4(uint* r, uint addr){
    asm volatile("ldmatrix.sync.aligned.m8n8.x4.shared.b16 {%0,%1,%2,%3}, [%4];"
        : "=r"(r[0]), "=r"(r[1]), "=r"(r[2]), "=r"(r[3]) : "r"(addr));
}
__device__ __forceinline__ void cp16(uint saddr, const void* g){
    asm volatile("cp.async.cg.shared.global [%0], [%1], 16;" :: "r"(saddr), "l"(g));
}
#define CP_COMMIT() asm volatile("cp.async.commit_group;" ::: "memory")
#define CP_WAIT0()  asm volatile("cp.async.wait_group 0;" ::: "memory")

// ---------------------------------------------------------------- k_prep
__global__ void k_prep(const float* __restrict__ X)
{
    int gid = blockIdx.x * blockDim.x + threadIdx.x;
    if (gid >= NNODE) return;
    const float* x = X + gid*12;
    float Nx=x[0],  Ny=x[1],  Nz=x[2];
    float Cax=x[3], Cay=x[4], Caz=x[5];
    float Cx=x[6],  Cy=x[7],  Cz=x[8];
    float Ox=x[9],  Oy=x[10], Oz=x[11];
    float bx=Cax-Nx, by=Cay-Ny, bz=Caz-Nz;
    float cx=Cx-Cax, cy=Cy-Cay, cz=Cz-Caz;
    float ax = by*cz - bz*cy;
    float ay = bz*cx - bx*cz;
    float az = bx*cy - by*cx;
    float Cbx = -0.58273431f*ax + 0.56802827f*bx - 0.54067466f*cx + Cax;
    float Cby = -0.58273431f*ay + 0.56802827f*by - 0.54067466f*cy + Cay;
    float Cbz = -0.58273431f*az + 0.56802827f*bz - 0.54067466f*cz + Caz;
    float* o = g_coords5 + gid*15;
    o[0]=Nx;   o[1]=Ny;   o[2]=Nz;
    o[3]=Cax;  o[4]=Cay;  o[5]=Caz;
    o[6]=Cx;   o[7]=Cy;   o[8]=Cz;
    o[9]=Ox;   o[10]=Oy;  o[11]=Oz;
    o[12]=Cbx; o[13]=Cby; o[14]=Cbz;
    g_ca[gid*3+0]=Cax; g_ca[gid*3+1]=Cay; g_ca[gid*3+2]=Caz;
}

// ---------------------------------------------------------------- k_wt
// W^T fp16: g_wt[n*416 + k] = half(We[k*128 + n]); coalesced writes
__global__ void k_wt(const float* __restrict__ We)
{
    int idx = blockIdx.x * blockDim.x + threadIdx.x;
    if (idx >= 416*128) return;
    int n = idx / 416, k = idx - n*416;
    g_wt[idx] = __float2half(We[k*128 + n]);
}

// ---------------------------------------------------------------- k_topk
// exact ascending top-30; hierarchical: 8 warps own 256-key segments,
// only the segment that lost its min rescans each round.
__global__ void __launch_bounds__(256) k_topk(
    const float* __restrict__ mask,
    float* __restrict__ out_tail,
    int write_tail)
{
    __shared__ ull   keys[NNN];
    __shared__ ull   wmin[8];
    __shared__ float fred[8];
    __shared__ int   s_owner;

    int gid = blockIdx.x;
    int b   = gid >> 11;
    int tid = threadIdx.x;
    int lid = tid & 31, wid = tid >> 5;

    float cix = g_ca[gid*3+0], ciy = g_ca[gid*3+1], ciz = g_ca[gid*3+2];
    float mi  = mask[gid];
    const float* cab = g_ca + (size_t)(b << 11) * 3;
    const float* mb  = mask + (b << 11);

    float lmax = 0.f;
    for (int j = tid; j < NNN; j += 256) {
        float dx = cab[j*3+0]-cix, dy = cab[j*3+1]-ciy, dz = cab[j*3+2]-ciz;
        float D  = mi * mb[j] * __fsqrt_rn(dx*dx + dy*dy + dz*dz + 1e-6f);
        keys[j]  = ((ull)__float_as_uint(D) << 32) | (unsigned)j;
        lmax = fmaxf(lmax, D);
    }
    #pragma unroll
    for (int m = 16; m > 0; m >>= 1)
        lmax = fmaxf(lmax, __shfl_xor_sync(0xFFFFFFFFu, lmax, m));
    if (lid == 0) fred[wid] = lmax;
    __syncthreads();
    float Dmax = fred[0];
    #pragma unroll
    for (int w = 1; w < 8; w++) Dmax = fmaxf(Dmax, fred[w]);

    for (int j = tid; j < NNN; j += 256) {
        float m2 = mi * mb[j];
        if (m2 != 1.0f) {
            float D = __uint_as_float((unsigned)(keys[j] >> 32));
            float Da = D + (1.0f - m2) * Dmax;
            keys[j] = ((ull)__float_as_uint(Da) << 32) | (unsigned)j;
        }
    }
    __syncthreads();

    {
        ull lm = 0xFFFFFFFFFFFFFFFFull;
        int base = wid << 8;
        #pragma unroll
        for (int r = 0; r < 8; r++) {
            ull v = keys[base + lid + (r<<5)];
            lm = (v < lm) ? v : lm;
        }
        #pragma unroll
        for (int m = 16; m > 0; m >>= 1) {
            ull o = __shfl_xor_sync(0xFFFFFFFFu, lm, m);
            lm = (o < lm) ? o : lm;
        }
        if (lid == 0) wmin[wid] = lm;
    }
    __syncthreads();

    for (int k = 0; k < KK; k++) {
        if (tid == 0) {
            ull best = wmin[0]; int ow = 0;
            #pragma unroll
            for (int w = 1; w < 8; w++) {
                ull v = wmin[w];
                if (v < best) { best = v; ow = w; }
            }
            int bj = (int)(best & 0xFFFFFFFFull);
            g_eidx[gid*KK + k] = bj;
            if (write_tail) out_tail[gid*KK + k] = (float)bj;
            keys[bj] = 0xFFFFFFFFFFFFFFFFull;
            s_owner = ow;
        }
        __syncthreads();
        if (wid == s_owner) {
            ull lm = 0xFFFFFFFFFFFFFFFFull;
            int base = wid << 8;
            #pragma unroll
            for (int r = 0; r < 8; r++) {
                ull v = keys[base + lid + (r<<5)];
                lm = (v < lm) ? v : lm;
            }
            #pragma unroll
            for (int m = 16; m > 0; m >>= 1) {
                ull o = __shfl_xor_sync(0xFFFFFFFFu, lm, m);
                lm = (o < lm) ? o : lm;
            }
            if (lid == 0) wmin[wid] = lm;
        }
        __syncthreads();
    }
}

// ---------------------------------------------------------------- k_edge
// D[128 edges,128 ch] = A[128,416] * W^T[128,416], fp16 mma.sync m16n8k16,
// ldmatrix frags, cp.async double-buffered B, pipelined A-gen, fused LN.
extern __shared__ __align__(16) char sm_raw[];

__global__ void __launch_bounds__(256, 2) k_edge(
    const int*   __restrict__ ridx,
    const int*   __restrict__ chain,
    const float* __restrict__ Wp,
    const float* __restrict__ bp,
    const float* __restrict__ lns,
    const float* __restrict__ lno,
    float*       __restrict__ out)
{
    // smem: A0 A1 B0 B1, each 128 rows x 80B
    __shared__ int   s_gi[EPB], s_gj[EPB], s_dp[EPB];
    __shared__ float s_lns[128], s_lno[128], s_bp[16];

    int tid = threadIdx.x, wid = tid >> 5, lid = tid & 31;
    int e0  = blockIdx.x * EPB;

    uint sb = (uint)__cvta_generic_to_shared(sm_raw);
    uint Aoff[2] = { sb,           sb + 10240 };
    uint Boff[2] = { sb + 20480,   sb + 30720 };

    if (tid < EPB) {
        int edge = e0 + tid;
        int node = edge / KK;
        int bb   = node >> 11;
        int gj   = (bb << 11) + g_eidx[edge];
        s_gi[tid] = node; s_gj[tid] = gj;
        int off = ridx[node] - ridx[gj];
        s_dp[tid] = (chain[node] == chain[gj]) ? min(max(off + 32, 0), 64) : 65;
        s_lns[tid] = lns[tid]; s_lno[tid] = lno[tid];
        if (tid < 16) s_bp[tid] = bp[tid];
    }
    __syncthreads();

    int fe  = tid >> 1;     // feature row (edge)
    int fbl = tid & 1;      // 16-half half of the 32-wide chunk

    // A-gen into buffer buf for chunk c
    auto gen_A = [&](int c, int buf) {
        half2* dst = (half2*)(sm_raw + (buf ? 10240 : 0) + fe*ROWB + fbl*32);
        int fb = 2*c + fbl;
        if (fb == 0) {
            const float* wrow = Wp + s_dp[fe]*16;
            #pragma unroll
            for (int jj = 0; jj < 8; jj++)
                dst[jj] = __floats2half2_rn(wrow[2*jj] + s_bp[2*jj],
                                            wrow[2*jj+1] + s_bp[2*jj+1]);
        } else {
            int p = fb - 1;
            const float* pa = g_coords5 + s_gi[fe]*15 + c_pa[p]*3;
            const float* pq = g_coords5 + s_gj[fe]*15 + c_pb[p]*3;
            float dx = pa[0]-pq[0], dy = pa[1]-pq[1], dz = pa[2]-pq[2];
            float d  = __fsqrt_rn(dx*dx + dy*dy + dz*dz + 1e-6f);
            #pragma unroll
            for (int jj = 0; jj < 8; jj++) {
                float u0 = (d - (2.0f + RBF_DEL*(float)(2*jj)))   * RBF_INVS;
                float u1 = (d - (2.0f + RBF_DEL*(float)(2*jj+1))) * RBF_INVS;
                dst[jj] = __floats2half2_rn(__expf(-u0*u0), __expf(-u1*u1));
            }
        }
    };
    // B chunk c via cp.async (2 x 16B per thread)
    auto stage_B = [&](int c, int buf) {
        const char* gb = (const char*)g_wt;
        #pragma unroll
        for (int q = 0; q < 2; q++) {
            int f = tid*2 + q;          // 0..511
            int row = f >> 2, seg = f & 3;
            cp16(Boff[buf] + row*ROWB + seg*16, gb + row*832 + c*64 + seg*16);
        }
        CP_COMMIT();
    };

    // warp tiling: 4(M) x 2(N); per warp 32m x 64n
    int mw = wid >> 1, nw = wid & 1;
    int m0 = mw << 5, n0 = nw << 6;

    // per-lane ldmatrix row/col offsets
    int arA = (lid & 7) + ((lid >> 3) & 1) * 8;
    int caA = ((lid >> 4) & 1) * 16;          // bytes
    int arB = (lid & 7) + ((lid >> 4) & 1) * 8;
    int caB = ((lid >> 3) & 1) * 16;          // bytes

    float acc[2][8][4];
    #pragma unroll
    for (int mt = 0; mt < 2; mt++)
        #pragma unroll
        for (int nt = 0; nt < 8; nt++)
            #pragma unroll
            for (int q = 0; q < 4; q++) acc[mt][nt][q] = 0.f;

    // prologue: stage chunk 0
    stage_B(0, 0);
    gen_A(0, 0);
    CP_WAIT0();
    __syncthreads();

    for (int c = 0; c < NCH; ++c) {
        int buf = c & 1, nbuf = buf ^ 1;
        if (c + 1 < NCH) stage_B(c + 1, nbuf);

        // MMA on buffer buf
        #pragma unroll
        for (int ks = 0; ks < 2; ks++) {
            int kb = ks * 32;   // bytes
            uint a[2][4];
            #pragma unroll
            for (int mt = 0; mt < 2; mt++)
                ldmx4(a[mt], Aoff[buf] + (uint)(m0 + 16*mt + arA)*ROWB + caA + kb);
            uint bf[8][2];
            #pragma unroll
            for (int ntp = 0; ntp < 4; ntp++) {
                uint r[4];
                ldmx4(r, Boff[buf] + (uint)(n0 + 16*ntp + arB)*ROWB + caB + kb);
                bf[2*ntp][0]   = r[0]; bf[2*ntp][1]   = r[1];
                bf[2*ntp+1][0] = r[2]; bf[2*ntp+1][1] = r[3];
            }
            #pragma unroll
            for (int mt = 0; mt < 2; mt++)
                #pragma unroll
                for (int nt = 0; nt < 8; nt++)
                    mma16(acc[mt][nt], a[mt], bf[nt]);
        }

        if (c + 1 < NCH) gen_A(c + 1, nbuf);
        CP_WAIT0();
        __syncthreads();
    }

    // ---- fused LayerNorm epilogue
    int lg = lid >> 2, lt = lid & 3;
    float2* red = (float2*)sm_raw;   // [128 rows][2 halves]
    #pragma unroll
    for (int mt = 0; mt < 2; mt++) {
        #pragma unroll
        for (int hf = 0; hf < 2; hf++) {
            float s1 = 0.f, s2 = 0.f;
            #pragma unroll
            for (int nt = 0; nt < 8; nt++) {
                float v0 = acc[mt][nt][2*hf], v1 = acc[mt][nt][2*hf+1];
                s1 += v0 + v1; s2 += v0*v0 + v1*v1;
            }
            #pragma unroll
            for (int m = 1; m < 4; m <<= 1) {
                s1 += __shfl_xor_sync(0xFFFFFFFFu, s1, m);
                s2 += __shfl_xor_sync(0xFFFFFFFFu, s2, m);
            }
            if (lt == 0) {
                int row = m0 + 16*mt + 8*hf + lg;
                red[row*2 + nw] = make_float2(s1, s2);
            }
        }
    }
    __syncthreads();

    #pragma unroll
    for (int mt = 0; mt < 2; mt++) {
        #pragma unroll
        for (int hf = 0; hf < 2; hf++) {
            int row = m0 + 16*mt + 8*hf + lg;
            float2 r0 = red[row*2 + 0], r1 = red[row*2 + 1];
            float s1 = r0.x + r1.x, s2 = r0.y + r1.y;
            float mean = s1 * (1.0f/128.0f);
            float var  = s2 * (1.0f/128.0f) - mean*mean;
            float rstd = rsqrtf(var + 1e-5f);
            float* orow = out + (size_t)(e0 + row) * 128;
            #pragma unroll
            for (int nt = 0; nt < 8; nt++) {
                int col = n0 + nt*8 + 2*lt;
                float v0 = acc[mt][nt][2*hf], v1 = acc[mt][nt][2*hf+1];
                float2 o;
                o.x = (v0 - mean)*rstd*s_lns[col]   + s_lno[col];
                o.y = (v1 - mean)*rstd*s_lns[col+1] + s_lno[col+1];
                *(float2*)(orow + col) = o;
            }
        }
    }
}

// ----------------------------------------------------------------
extern "C" void kernel_launch(void* const* d_in, const int* in_sizes, int n_in,
                              void* d_out, int out_size)
{
    const float* X      = (const float*)d_in[0];
    const float* mask   = (const float*)d_in[1];
    const int*   ridx   = (const int*)  d_in[2];
    const int*   chain  = (const int*)  d_in[3];
    const float* W_pos  = (const float*)d_in[4];
    const float* b_pos  = (const float*)d_in[5];
    const float* W_edge = (const float*)d_in[6];
    const float* ln_s   = (const float*)d_in[7];
    const float* ln_o   = (const float*)d_in[8];
    float* out = (float*)d_out;

    int write_tail = (out_size > NEDGE*128) ? 1 : 0;
    float* tail = out + (size_t)NEDGE*128;

    int smem_bytes = 4 * 128 * ROWB;   // 40960 B

    k_prep<<<(NNODE + 255)/256, 256>>>(X);
    k_wt<<<(416*128 + 255)/256, 256>>>(W_edge);
    k_topk<<<NNODE, 256>>>(mask, tail, write_tail);
    k_edge<<<NEDGE/EPB, 256, smem_bytes>>>(ridx, chain, W_pos, b_pos,
                                           ln_s, ln_o, out);
}